// round 4
// baseline (speedup 1.0000x reference)
#include <cuda_runtime.h>

// SimpleTP: FullTensorProduct('1x1o','1x1o') of frac with itself, summed over N.
// Reduces to 6 quadratic moments s_ij = sum_n frac[n,i]*frac[n,j] (i<=j),
// then a fixed linear map to the 9 outputs (cross part is identically 0).
// Single kernel: grid-wide streaming + threadfence-reduction last-block epilogue.

#define BLK 256
#define GRID_MAIN 1184          // ~8 blocks/SM on 148-SM B200
#define NACC 6

// Scratch partials, SoA: g_part[k*GRID_MAIN + b]  (coalesced re-read)
__device__ float g_part[NACC * GRID_MAIN];
__device__ unsigned int g_count = 0;

__device__ __forceinline__ void acc3(float a, float b, float c,
                                     float& s00, float& s11, float& s22,
                                     float& s01, float& s02, float& s12) {
    s00 = fmaf(a, a, s00);
    s11 = fmaf(b, b, s11);
    s22 = fmaf(c, c, s22);
    s01 = fmaf(a, b, s01);
    s02 = fmaf(a, c, s02);
    s12 = fmaf(b, c, s12);
}

__device__ __forceinline__ void acc_vec3(const float4& v0, const float4& v1, const float4& v2,
                                         float& s00, float& s11, float& s22,
                                         float& s01, float& s02, float& s12) {
    acc3(v0.x, v0.y, v0.z, s00, s11, s22, s01, s02, s12);
    acc3(v0.w, v1.x, v1.y, s00, s11, s22, s01, s02, s12);
    acc3(v1.z, v1.w, v2.x, s00, s11, s22, s01, s02, s12);
    acc3(v2.y, v2.z, v2.w, s00, s11, s22, s01, s02, s12);
}

__global__ __launch_bounds__(BLK) void tp_kernel(const float* __restrict__ in,
                                                 int total_floats,
                                                 float* __restrict__ out) {
    const float4* __restrict__ in4 = (const float4*)in;
    const int num_groups8 = total_floats / 24;   // groups of 8 rows (6 float4s)

    float s00 = 0.f, s11 = 0.f, s22 = 0.f, s01 = 0.f, s02 = 0.f, s12 = 0.f;

    int tid = blockIdx.x * BLK + threadIdx.x;
    int stride = gridDim.x * BLK;

    for (int g = tid; g < num_groups8; g += stride) {
        const float4* p = in4 + 6 * (size_t)g;
        float4 v0 = p[0];
        float4 v1 = p[1];
        float4 v2 = p[2];
        float4 v3 = p[3];
        float4 v4 = p[4];
        float4 v5 = p[5];
        acc_vec3(v0, v1, v2, s00, s11, s22, s01, s02, s12);
        acc_vec3(v3, v4, v5, s00, s11, s22, s01, s02, s12);
    }

    // warp reduction
    #pragma unroll
    for (int o = 16; o > 0; o >>= 1) {
        s00 += __shfl_down_sync(0xffffffffu, s00, o);
        s11 += __shfl_down_sync(0xffffffffu, s11, o);
        s22 += __shfl_down_sync(0xffffffffu, s22, o);
        s01 += __shfl_down_sync(0xffffffffu, s01, o);
        s02 += __shfl_down_sync(0xffffffffu, s02, o);
        s12 += __shfl_down_sync(0xffffffffu, s12, o);
    }

    __shared__ float sm[NACC][BLK / 32];
    int lane = threadIdx.x & 31;
    int w = threadIdx.x >> 5;
    if (lane == 0) {
        sm[0][w] = s00; sm[1][w] = s11; sm[2][w] = s22;
        sm[3][w] = s01; sm[4][w] = s02; sm[5][w] = s12;
    }
    __syncthreads();

    // one thread per accumulator folds the 8 warp partials and publishes
    if (threadIdx.x < NACC) {
        float t = 0.f;
        #pragma unroll
        for (int i = 0; i < BLK / 32; i++) t += sm[threadIdx.x][i];
        g_part[threadIdx.x * GRID_MAIN + blockIdx.x] = t;
    }

    // ---- last-block epilogue (threadfence reduction) ----
    __shared__ bool is_last;
    __threadfence();
    if (threadIdx.x == 0) {
        unsigned int prev = atomicAdd(&g_count, 1u);
        is_last = (prev == (unsigned int)(gridDim.x - 1));
    }
    __syncthreads();
    if (!is_last) return;

    // This block sees all partials (threadfence in writers + atomic ordering).
    const volatile float* vpart = (const volatile float*)g_part;
    float s[NACC];
    #pragma unroll
    for (int k = 0; k < NACC; k++) s[k] = 0.f;

    for (int b = threadIdx.x; b < GRID_MAIN; b += BLK) {
        #pragma unroll
        for (int k = 0; k < NACC; k++) s[k] += vpart[k * GRID_MAIN + b];
    }

    // tail rows (not covered by groups-of-8), thread 0 only (<= 7 rows)
    if (threadIdx.x == 0) {
        int num_rows = total_floats / 3;
        int covered = (num_rows / 8) * 8;
        for (int r = covered; r < num_rows; r++) {
            float a = in[3 * r + 0], b = in[3 * r + 1], c = in[3 * r + 2];
            s[0] += a * a; s[1] += b * b; s[2] += c * c;
            s[3] += a * b; s[4] += a * c; s[5] += b * c;
        }
    }

    // block reduce (fixed order -> deterministic)
    #pragma unroll
    for (int o = 16; o > 0; o >>= 1) {
        #pragma unroll
        for (int k = 0; k < NACC; k++) s[k] += __shfl_down_sync(0xffffffffu, s[k], o);
    }
    __shared__ float sm2[NACC][BLK / 32];
    if (lane == 0) {
        #pragma unroll
        for (int k = 0; k < NACC; k++) sm2[k][w] = s[k];
    }
    __syncthreads();

    if (threadIdx.x == 0) {
        float t[NACC];
        #pragma unroll
        for (int k = 0; k < NACC; k++) {
            t[k] = 0.f;
            #pragma unroll
            for (int i = 0; i < BLK / 32; i++) t[k] += sm2[k][i];
        }
        const float s00f = t[0], s11f = t[1], s22f = t[2];
        const float s01f = t[3], s02f = t[4], s12f = t[5];
        const float INV_SQRT3 = 0.57735026918962576f;
        const float SQRT2     = 1.41421356237309505f;
        const float INV_SQRT6 = 0.40824829046386302f;
        const float INV_SQRT2 = 0.70710678118654752f;

        out[0] = (s00f + s11f + s22f) * INV_SQRT3;        // 0e
        out[1] = 0.f;                                     // 1e: cross(x,x)=0
        out[2] = 0.f;
        out[3] = 0.f;
        out[4] = SQRT2 * s02f;                            // 2e m=-2
        out[5] = SQRT2 * s01f;                            // 2e m=-1
        out[6] = (2.f * s11f - s00f - s22f) * INV_SQRT6;  // 2e m=0
        out[7] = SQRT2 * s12f;                            // 2e m=+1
        out[8] = (s22f - s00f) * INV_SQRT2;               // 2e m=+2

        g_count = 0;   // reset for next graph replay
    }
}

extern "C" void kernel_launch(void* const* d_in, const int* in_sizes, int n_in,
                              void* d_out, int out_size) {
    const float* frac = (const float*)d_in[0];
    float* out = (float*)d_out;
    int total_floats = in_sizes[0];          // N*3

    tp_kernel<<<GRID_MAIN, BLK>>>(frac, total_floats, out);
}